// round 1
// baseline (speedup 1.0000x reference)
#include <cuda_runtime.h>
#include <cstdint>
#include <cstddef>

#define SEQLEN 512
#define BATCH  64
#define HID    512
#define INP    512
#define G4     2048
#define NB_REC 128
#define NT_REC 128

// ---------------- device scratch (statically allocated; no runtime alloc) ----------------
__device__ float g_xproj[(size_t)SEQLEN * BATCH * G4];   // 256 MB: x @ W_ih^T + bias
__device__ float g_hbuf[2][BATCH * HID];                 // double-buffered hidden state
__device__ unsigned g_count;                             // grid barrier arrival count
__device__ unsigned g_gen;                               // grid barrier generation

// ---------------- packed fp32x2 FMA (full-rate fp32 on sm_103a) ----------------
__device__ __forceinline__ void fma2(unsigned long long& d, unsigned long long a,
                                     unsigned long long b) {
    asm("fma.rn.f32x2 %0, %1, %2, %0;" : "+l"(d) : "l"(a), "l"(b));
}
__device__ __forceinline__ float f2sum(unsigned long long v) {
    float lo, hi;
    asm("mov.b64 {%0, %1}, %2;" : "=f"(lo), "=f"(hi) : "l"(v));
    return lo + hi;
}

__device__ __forceinline__ float sigf(float x) { return 1.0f / (1.0f + __expf(-x)); }
__device__ __forceinline__ float tanhf_acc(float x) {
    return 2.0f / (1.0f + __expf(-2.0f * x)) - 1.0f;
}

// =====================================================================================
// Kernel 1: x_proj[m][n] = sum_k input[m][k] * W_ih[n][k] + (bias_ih[n] + bias_hh[n])
// M = S*B = 32768, N = 4H = 2048, K = 512. Block tile 128x64, thread tile 8Mx4N,
// k-paired f32x2 accumulation (both operand layouts are k-contiguous => natural pairing).
// =====================================================================================
__global__ __launch_bounds__(256, 2)
void gemm_xproj(const float* __restrict__ A, const float* __restrict__ W,
                const float* __restrict__ bih, const float* __restrict__ bhh)
{
    // row stride 34 floats (136B == 8 mod 128) => conflict-free 8B compute loads
    __shared__ float As[128 * 34];
    __shared__ float Bs[64 * 34];

    const int tid = threadIdx.x;
    const int tm  = tid >> 4;      // 0..15 -> 8 M rows each
    const int tn  = tid & 15;      // 0..15 -> N cols {tn, tn+16, tn+32, tn+48}
    const int m0  = blockIdx.x * 128;
    const int n0  = blockIdx.y * 64;

    unsigned long long acc[8][4];
    #pragma unroll
    for (int i = 0; i < 8; i++)
        #pragma unroll
        for (int j = 0; j < 4; j++) acc[i][j] = 0ull;

    for (int k0 = 0; k0 < INP; k0 += 32) {
        #pragma unroll
        for (int i = 0; i < 8; i++) {          // A tile: 128x32 = 2048 float2
            int idx = tid + i * 256;
            int r = idx >> 4, c2 = (idx & 15) * 2;
            *(float2*)&As[r * 34 + c2] =
                *(const float2*)&A[(size_t)(m0 + r) * INP + k0 + c2];
        }
        #pragma unroll
        for (int i = 0; i < 4; i++) {          // B tile: 64x32 = 1024 float2
            int idx = tid + i * 256;
            int r = idx >> 4, c2 = (idx & 15) * 2;
            *(float2*)&Bs[r * 34 + c2] =
                *(const float2*)&W[(size_t)(n0 + r) * INP + k0 + c2];
        }
        __syncthreads();

        #pragma unroll
        for (int kp = 0; kp < 16; kp++) {
            unsigned long long av[8], bv[4];
            #pragma unroll
            for (int i = 0; i < 8; i++)
                av[i] = *(const unsigned long long*)&As[(tm * 8 + i) * 34 + kp * 2];
            #pragma unroll
            for (int j = 0; j < 4; j++)
                bv[j] = *(const unsigned long long*)&Bs[(tn + j * 16) * 34 + kp * 2];
            #pragma unroll
            for (int i = 0; i < 8; i++)
                #pragma unroll
                for (int j = 0; j < 4; j++) fma2(acc[i][j], av[i], bv[j]);
        }
        __syncthreads();
    }

    #pragma unroll
    for (int j = 0; j < 4; j++) {
        int n = n0 + tn + j * 16;
        float bias = bih[n] + bhh[n];
        #pragma unroll
        for (int i = 0; i < 8; i++) {
            g_xproj[(size_t)(m0 + tm * 8 + i) * G4 + n] = f2sum(acc[i][j]) + bias;
        }
    }
}

// =====================================================================================
// Kernel 2: persistent recurrence. 128 blocks = 4 batch-groups x 32 col-groups.
// Block (bi,cj): batch rows [16bi,16bi+16), hidden cols [16cj,16cj+16).
// W_hh slice (64 gate-rows x 512) lives in smem for all 512 steps; c-state in smem.
// Each step: load h (global, L2-only) -> smem, 16x64x512 GEMM in f32x2 with k-pair
// packing (warp = k-group), partial reduce via smem, elementwise LSTM update,
// write h_new to double-buffered global + output, software grid barrier.
// Thread owns all 4 gate types of one hidden column => no cross-thread gate combine.
// =====================================================================================
struct RecSmem {
    float Wsm[64][514];       // [type*16+jl][k]; stride 2056B == 8 mod 128: conflict-free
    float hs[16][516];        // [b][k]; broadcast loads
    float red[4][16][68];     // [kgroup][jl][b*4+type] (+pad)
    float cs[16][16];         // cell state slice
};

__global__ __launch_bounds__(NT_REC, 1)
void lstm_rec(const float* __restrict__ h0, const float* __restrict__ c0,
              const float* __restrict__ Whh, float* __restrict__ out, int write_hc)
{
    extern __shared__ char smem_raw[];
    RecSmem* sm = (RecSmem*)smem_raw;

    const int tid  = threadIdx.x;
    const int bi   = blockIdx.x >> 5;   // 0..3
    const int cj   = blockIdx.x & 31;   // 0..31
    const int lane = tid & 31;
    const int kg   = tid >> 5;          // warp = k-group (k range 128)
    const int jl   = lane & 15;         // hidden column within group
    const int bq   = lane >> 4;         // 0..1 -> 8 batch rows each
    const int b0   = bq * 8;

    // ---- load W_hh slice: rows {ty*512 + cj*16 + j} for ty in 0..3, j in 0..15 ----
    for (int i = tid; i < 64 * 256; i += NT_REC) {
        int r = i >> 8;                 // 0..63 = ty*16 + j
        int kp2 = (i & 255) * 2;
        int ty = r >> 4, j = r & 15;
        *(float2*)&sm->Wsm[r][kp2] =
            *(const float2*)&Whh[(size_t)(ty * HID + cj * 16 + j) * HID + kp2];
    }
    // ---- load c0 slice ----
    #pragma unroll
    for (int u = 0; u < 2; u++) {
        int cell = tid + u * 128;
        int b = cell >> 4, j = cell & 15;
        sm->cs[b][j] = c0[(size_t)(bi * 16 + b) * HID + cj * 16 + j];
    }
    __syncthreads();

    for (int t = 0; t < SEQLEN; t++) {
        // ---- phase A: stage h_t into smem (L2-only loads; other SMs wrote it) ----
        const float* hsrc = (t == 0) ? h0 : g_hbuf[t & 1];
        const float* hrow = hsrc + (size_t)(bi * 16) * HID;
        for (int i = tid; i < 16 * 256; i += NT_REC) {
            int b = i >> 8;
            int kp2 = (i & 255) * 2;
            float2 v = __ldcg((const float2*)(hrow + (size_t)b * HID + kp2));
            *(float2*)&sm->hs[b][kp2] = v;
        }
        __syncthreads();

        // ---- phase B: gates_partial[b][ty] over this warp's k range ----
        unsigned long long acc[8][4];
        #pragma unroll
        for (int i = 0; i < 8; i++)
            #pragma unroll
            for (int j = 0; j < 4; j++) acc[i][j] = 0ull;

        const int kp0 = kg * 64;
        #pragma unroll 4
        for (int kp = kp0; kp < kp0 + 64; kp++) {
            unsigned long long wv[4], hv[8];
            #pragma unroll
            for (int ty = 0; ty < 4; ty++)
                wv[ty] = *(const unsigned long long*)&sm->Wsm[ty * 16 + jl][kp * 2];
            #pragma unroll
            for (int i = 0; i < 8; i++)
                hv[i] = *(const unsigned long long*)&sm->hs[b0 + i][kp * 2];
            #pragma unroll
            for (int i = 0; i < 8; i++)
                #pragma unroll
                for (int ty = 0; ty < 4; ty++) fma2(acc[i][ty], hv[i], wv[ty]);
        }
        #pragma unroll
        for (int i = 0; i < 8; i++) {
            float4 v;
            v.x = f2sum(acc[i][0]); v.y = f2sum(acc[i][1]);
            v.z = f2sum(acc[i][2]); v.w = f2sum(acc[i][3]);
            *(float4*)&sm->red[kg][jl][(b0 + i) * 4] = v;
        }
        __syncthreads();

        // ---- phase C: reduce k-groups, add x_proj, LSTM elementwise, write h ----
        #pragma unroll
        for (int u = 0; u < 2; u++) {
            int cell = tid + u * 128;
            int b = cell >> 4, j = cell & 15;
            float4 s = *(const float4*)&sm->red[0][j][b * 4];
            #pragma unroll
            for (int kk = 1; kk < 4; kk++) {
                float4 p = *(const float4*)&sm->red[kk][j][b * 4];
                s.x += p.x; s.y += p.y; s.z += p.z; s.w += p.w;
            }
            size_t xofs = ((size_t)t * BATCH + bi * 16 + b) * G4 + cj * 16 + j;
            float gi = s.x + g_xproj[xofs];
            float gf = s.y + g_xproj[xofs + HID];
            float gg = s.z + g_xproj[xofs + 2 * HID];
            float go = s.w + g_xproj[xofs + 3 * HID];
            float iv = sigf(gi), fv = sigf(gf);
            float gv = tanhf_acc(gg), ov = sigf(go);
            float cn = fv * sm->cs[b][j] + iv * gv;
            sm->cs[b][j] = cn;
            float hn = ov * tanhf_acc(cn);

            size_t hofs = (size_t)(bi * 16 + b) * HID + cj * 16 + j;
            g_hbuf[(t + 1) & 1][hofs] = hn;
            out[(size_t)t * (BATCH * HID) + hofs] = hn;
            if (write_hc && t == SEQLEN - 1) {
                out[(size_t)SEQLEN * BATCH * HID + hofs] = hn;                 // h_T
                out[(size_t)SEQLEN * BATCH * HID + BATCH * HID + hofs] = cn;   // c_T
            }
        }

        // ---- grid barrier (all 128 blocks co-resident: 1 block/SM, grid <= 148) ----
        __threadfence();
        __syncthreads();
        if (tid == 0) {
            unsigned old = *(volatile unsigned*)&g_gen;
            unsigned prev = atomicAdd(&g_count, 1u);
            if (prev == (unsigned)(gridDim.x - 1)) {
                g_count = 0u;
                __threadfence();
                *(volatile unsigned*)&g_gen = old + 1u;
            } else {
                while (*(volatile unsigned*)&g_gen == old) { }
            }
        }
        __syncthreads();
    }
}

// =====================================================================================
// launch
// =====================================================================================
extern "C" void kernel_launch(void* const* d_in, const int* in_sizes, int n_in,
                              void* d_out, int out_size)
{
    const float* input = (const float*)d_in[0];  // (S, B, I)
    const float* h0    = (const float*)d_in[1];  // (B, H)
    const float* c0    = (const float*)d_in[2];  // (B, H)
    const float* Wih   = (const float*)d_in[3];  // (1, 4H, I)
    const float* Whh   = (const float*)d_in[4];  // (1, 4H, H)
    const float* bih   = (const float*)d_in[5];  // (1, 4H)
    const float* bhh   = (const float*)d_in[6];  // (1, 4H)
    // d_in[7] = direction (always 0 since NUM_DIRECTIONS == 1)
    (void)in_sizes; (void)n_in;

    float* out = (float*)d_out;
    const int n_outputs = SEQLEN * BATCH * HID;
    int write_hc = (out_size >= n_outputs + 2 * BATCH * HID) ? 1 : 0;

    cudaFuncSetAttribute(lstm_rec, cudaFuncAttributeMaxDynamicSharedMemorySize,
                         (int)sizeof(RecSmem));

    gemm_xproj<<<dim3((SEQLEN * BATCH) / 128, G4 / 64), 256>>>(input, Wih, bih, bhh);
    lstm_rec<<<NB_REC, NT_REC, sizeof(RecSmem)>>>(h0, c0, Whh, out, write_hc);
}

// round 2
// speedup vs baseline: 1.2579x; 1.2579x over previous
#include <cuda_runtime.h>
#include <cstdint>
#include <cstddef>

#define SEQLEN 512
#define BATCH  64
#define HID    512
#define INP    512
#define G4     2048
#define NB_REC 128
#define NT_REC 256

// ---------------- device scratch ----------------
__device__ float g_xproj[(size_t)SEQLEN * BATCH * G4];   // x @ W_ih^T + bias
__device__ float g_hbuf[2][BATCH * HID];                 // double-buffered hidden state
__device__ int   g_flags[4][32];                         // per (bi, cj) progress flags

// ---------------- packed fp32x2 FMA ----------------
__device__ __forceinline__ void fma2(unsigned long long& d, unsigned long long a,
                                     unsigned long long b) {
    asm("fma.rn.f32x2 %0, %1, %2, %0;" : "+l"(d) : "l"(a), "l"(b));
}
__device__ __forceinline__ float f2sum(unsigned long long v) {
    float lo, hi;
    asm("mov.b64 {%0, %1}, %2;" : "=f"(lo), "=f"(hi) : "l"(v));
    return lo + hi;
}
__device__ __forceinline__ float sigf(float x) { return 1.0f / (1.0f + __expf(-x)); }
__device__ __forceinline__ float tanhf_acc(float x) {
    return 2.0f / (1.0f + __expf(-2.0f * x)) - 1.0f;
}
__device__ __forceinline__ unsigned smem_u32(const void* p) {
    unsigned a;
    asm("{ .reg .u64 t; cvta.to.shared.u64 t, %1; cvt.u32.u64 %0, t; }" : "=r"(a) : "l"(p));
    return a;
}
__device__ __forceinline__ void cp16(unsigned dst, const void* src) {
    asm volatile("cp.async.cg.shared.global [%0], [%1], 16;" :: "r"(dst), "l"(src));
}

// =====================================================================================
// init: zero progress flags (graph-replayed every call)
// =====================================================================================
__global__ void init_flags() {
    if (threadIdx.x < 128) ((int*)g_flags)[threadIdx.x] = 0;
}

// =====================================================================================
// Kernel 1: x_proj = input @ W_ih^T + (b_ih + b_hh).  M=32768, N=2048, K=512.
// Block tile 128x64, thread tile 8Mx4N, f32x2 accumulation, cp.async double-buffer.
// Row stride 36 floats (144B, 16B-aligned) for LDGSTS destinations.
// =====================================================================================
#define ASTRIDE 36
#define ASZ (128 * ASTRIDE)
#define BSZ (64 * ASTRIDE)

__global__ __launch_bounds__(256, 2)
void gemm_xproj(const float* __restrict__ A, const float* __restrict__ W,
                const float* __restrict__ bih, const float* __restrict__ bhh)
{
    extern __shared__ float smem[];
    float* Asm[2] = { smem,             smem + (ASZ + BSZ) };
    float* Bsm[2] = { smem + ASZ,       smem + (ASZ + BSZ) + ASZ };

    const int tid = threadIdx.x;
    const int tm  = tid >> 4;
    const int tn  = tid & 15;
    const int m0  = blockIdx.x * 128;
    const int n0  = blockIdx.y * 64;

    // cp.async tile copy: tile kt (k0 = kt*32) into buffer sel
    auto copy_tile = [&](int kt, int sel) {
        const int k0 = kt * 32;
        unsigned abase = smem_u32(Asm[sel]);
        unsigned bbase = smem_u32(Bsm[sel]);
        #pragma unroll
        for (int i = 0; i < 4; i++) {            // A: 128 rows x 32 fl = 1024 x 16B
            int idx = tid + i * 256;
            int r = idx >> 3, c = (idx & 7) * 4;
            cp16(abase + (r * ASTRIDE + c) * 4, &A[(size_t)(m0 + r) * INP + k0 + c]);
        }
        #pragma unroll
        for (int i = 0; i < 2; i++) {            // B: 64 rows x 32 fl = 512 x 16B
            int idx = tid + i * 256;
            int r = idx >> 3, c = (idx & 7) * 4;
            cp16(bbase + (r * ASTRIDE + c) * 4, &W[(size_t)(n0 + r) * INP + k0 + c]);
        }
        asm volatile("cp.async.commit_group;");
    };

    unsigned long long acc[8][4];
    #pragma unroll
    for (int i = 0; i < 8; i++)
        #pragma unroll
        for (int j = 0; j < 4; j++) acc[i][j] = 0ull;

    copy_tile(0, 0);

    for (int kt = 0; kt < INP / 32; kt++) {
        asm volatile("cp.async.wait_group 0;");
        __syncthreads();
        if (kt + 1 < INP / 32) copy_tile(kt + 1, (kt + 1) & 1);

        const float* As = Asm[kt & 1];
        const float* Bs = Bsm[kt & 1];
        #pragma unroll
        for (int kp = 0; kp < 16; kp++) {
            unsigned long long av[8], bv[4];
            #pragma unroll
            for (int i = 0; i < 8; i++)
                av[i] = *(const unsigned long long*)&As[(tm * 8 + i) * ASTRIDE + kp * 2];
            #pragma unroll
            for (int j = 0; j < 4; j++)
                bv[j] = *(const unsigned long long*)&Bs[(tn + j * 16) * ASTRIDE + kp * 2];
            #pragma unroll
            for (int i = 0; i < 8; i++)
                #pragma unroll
                for (int j = 0; j < 4; j++) fma2(acc[i][j], av[i], bv[j]);
        }
        __syncthreads();
    }

    #pragma unroll
    for (int j = 0; j < 4; j++) {
        int n = n0 + tn + j * 16;
        float bias = bih[n] + bhh[n];
        #pragma unroll
        for (int i = 0; i < 8; i++)
            g_xproj[(size_t)(m0 + tm * 8 + i) * G4 + n] = f2sum(acc[i][j]) + bias;
    }
}

// =====================================================================================
// Kernel 2: persistent recurrence. 128 blocks = 4 batch-groups x 32 col-groups.
// 256 threads = 8 warps = 8 k-groups of 64 k. Thread-per-output-cell in phase C,
// cell state in a register, xproj prefetched, per-bi-group flag barrier.
// =====================================================================================
struct RecSmem {
    float Wsm[64][514];       // [ty*16+j][k]
    float hs[16][516];        // [b][k]
    float red[8][16][68];     // [kgroup][j][b*4+ty]
};

__global__ __launch_bounds__(NT_REC, 1)
void lstm_rec(const float* __restrict__ h0, const float* __restrict__ c0,
              const float* __restrict__ Whh, float* __restrict__ out, int write_hc)
{
    extern __shared__ char smem_raw[];
    RecSmem* sm = (RecSmem*)smem_raw;

    const int tid  = threadIdx.x;
    const int bi   = blockIdx.x >> 5;   // 0..3   batch group
    const int cj   = blockIdx.x & 31;   // 0..31  hidden-col group
    const int lane = tid & 31;
    const int kg   = tid >> 5;          // 0..7   warp = k-group of 64 k (32 kp)
    const int jl   = lane & 15;
    const int b0   = (lane >> 4) * 8;

    // phase-C cell owned by this thread
    const int cb = tid >> 4;            // 0..15 batch row in group
    const int cjl = tid & 15;           // 0..15 hidden col in group
    const size_t hofs = (size_t)(bi * 16 + cb) * HID + cj * 16 + cjl;

    // ---- resident W_hh slice ----
    for (int i = tid; i < 64 * 256; i += NT_REC) {
        int r = i >> 8;                 // ty*16 + j
        int kp2 = (i & 255) * 2;
        int ty = r >> 4, j = r & 15;
        *(float2*)&sm->Wsm[r][kp2] =
            *(const float2*)&Whh[(size_t)(ty * HID + cj * 16 + j) * HID + kp2];
    }
    float creg = c0[hofs];
    __syncthreads();

    volatile int* flags = (volatile int*)&g_flags[bi][0];

    for (int t = 0; t < SEQLEN; t++) {
        // ---- prefetch x_proj gate values for this thread's cell (independent of h) ----
        size_t xofs = ((size_t)t * BATCH + bi * 16 + cb) * G4 + cj * 16 + cjl;
        float xg0 = __ldcg(&g_xproj[xofs]);
        float xg1 = __ldcg(&g_xproj[xofs + HID]);
        float xg2 = __ldcg(&g_xproj[xofs + 2 * HID]);
        float xg3 = __ldcg(&g_xproj[xofs + 3 * HID]);

        // ---- wait for h_t producers (32 blocks of this bi group) ----
        if (t > 0) {
            if (tid < 32) { while (flags[tid] < t) { } }
            __threadfence();
        }
        __syncthreads();

        // ---- stage h_t into smem (L2 loads; written by other SMs) ----
        const float* hsrc = (t == 0) ? h0 : g_hbuf[t & 1];
        const float* hrow = hsrc + (size_t)(bi * 16) * HID;
        #pragma unroll
        for (int u = 0; u < 16; u++) {
            int i = tid + u * NT_REC;
            int b = i >> 8;
            int kp2 = (i & 255) * 2;
            float2 v = __ldcg((const float2*)(hrow + (size_t)b * HID + kp2));
            *(float2*)&sm->hs[b][kp2] = v;
        }
        __syncthreads();

        // ---- partial gates over this warp's 64-k range ----
        unsigned long long acc[8][4];
        #pragma unroll
        for (int i = 0; i < 8; i++)
            #pragma unroll
            for (int j = 0; j < 4; j++) acc[i][j] = 0ull;

        const int kp0 = kg * 32;
        #pragma unroll 4
        for (int kp = kp0; kp < kp0 + 32; kp++) {
            unsigned long long wv[4], hv[8];
            #pragma unroll
            for (int ty = 0; ty < 4; ty++)
                wv[ty] = *(const unsigned long long*)&sm->Wsm[ty * 16 + jl][kp * 2];
            #pragma unroll
            for (int i = 0; i < 8; i++)
                hv[i] = *(const unsigned long long*)&sm->hs[b0 + i][kp * 2];
            #pragma unroll
            for (int i = 0; i < 8; i++)
                #pragma unroll
                for (int ty = 0; ty < 4; ty++) fma2(acc[i][ty], hv[i], wv[ty]);
        }
        #pragma unroll
        for (int i = 0; i < 8; i++) {
            float4 v;
            v.x = f2sum(acc[i][0]); v.y = f2sum(acc[i][1]);
            v.z = f2sum(acc[i][2]); v.w = f2sum(acc[i][3]);
            *(float4*)&sm->red[kg][jl][(b0 + i) * 4] = v;
        }
        __syncthreads();

        // ---- reduce k-groups + LSTM elementwise (one cell per thread) ----
        float4 s = *(const float4*)&sm->red[0][cjl][cb * 4];
        #pragma unroll
        for (int kk = 1; kk < 8; kk++) {
            float4 p = *(const float4*)&sm->red[kk][cjl][cb * 4];
            s.x += p.x; s.y += p.y; s.z += p.z; s.w += p.w;
        }
        float iv = sigf(s.x + xg0);
        float fv = sigf(s.y + xg1);
        float gv = tanhf_acc(s.z + xg2);
        float ov = sigf(s.w + xg3);
        creg = fv * creg + iv * gv;
        float hn = ov * tanhf_acc(creg);

        g_hbuf[(t + 1) & 1][hofs] = hn;
        out[(size_t)t * (BATCH * HID) + hofs] = hn;
        if (write_hc && t == SEQLEN - 1) {
            out[(size_t)SEQLEN * BATCH * HID + hofs] = hn;
            out[(size_t)SEQLEN * BATCH * HID + BATCH * HID + hofs] = creg;
        }

        // ---- publish h_{t+1} ----
        __threadfence();
        __syncthreads();
        if (tid == 0) atomicExch((int*)&g_flags[bi][cj], t + 1);
    }
}

// =====================================================================================
extern "C" void kernel_launch(void* const* d_in, const int* in_sizes, int n_in,
                              void* d_out, int out_size)
{
    const float* input = (const float*)d_in[0];
    const float* h0    = (const float*)d_in[1];
    const float* c0    = (const float*)d_in[2];
    const float* Wih   = (const float*)d_in[3];
    const float* Whh   = (const float*)d_in[4];
    const float* bih   = (const float*)d_in[5];
    const float* bhh   = (const float*)d_in[6];
    (void)in_sizes; (void)n_in;

    float* out = (float*)d_out;
    const int n_outputs = SEQLEN * BATCH * HID;
    int write_hc = (out_size >= n_outputs + 2 * BATCH * HID) ? 1 : 0;

    static int configured = 0;
    const int gemm_smem = 2 * (ASZ + BSZ) * (int)sizeof(float);
    if (!configured) {
        cudaFuncSetAttribute(gemm_xproj, cudaFuncAttributeMaxDynamicSharedMemorySize,
                             gemm_smem);
        cudaFuncSetAttribute(lstm_rec, cudaFuncAttributeMaxDynamicSharedMemorySize,
                             (int)sizeof(RecSmem));
        configured = 1;
    }

    init_flags<<<1, 128>>>();
    gemm_xproj<<<dim3((SEQLEN * BATCH) / 128, G4 / 64), 256, gemm_smem>>>(
        input, Wih, bih, bhh);
    lstm_rec<<<NB_REC, NT_REC, sizeof(RecSmem)>>>(h0, c0, Whh, out, write_hc);
}